// round 6
// baseline (speedup 1.0000x reference)
#include <cuda_runtime.h>

#define SQ 2048
#define DM 1024
#define NH 16
#define DH 64
#define NEGV -1e18f

typedef unsigned long long ull;

// Scratch (device globals; no allocation allowed)
__device__ float g_Q[SQ * DM];   // Q; later reused as av partial-sum #1
__device__ float g_K[SQ * DM];
__device__ float g_V[SQ * DM];
__device__ float g_C[SQ * DM];   // av partial-sum #0

struct Proj3 {
    const float* W[3];
    const float* bias[3];
    float* C[3];
    float scale[3];
};

// ---- packed f32x2 helpers (sm_100+) ---------------------------------------
__device__ __forceinline__ ull splat2(float x) {
    ull r; asm("mov.b64 %0, {%1, %1};" : "=l"(r) : "f"(x)); return r;
}
__device__ __forceinline__ ull pack2(float lo, float hi) {
    ull r; asm("mov.b64 %0, {%1, %2};" : "=l"(r) : "f"(lo), "f"(hi)); return r;
}
__device__ __forceinline__ void ffma2(ull& d, ull a, ull b) {
    asm("fma.rn.f32x2 %0, %1, %2, %0;" : "+l"(d) : "l"(a), "l"(b));
}
__device__ __forceinline__ float2 unpack2(ull v) {
    float2 r; asm("mov.b64 {%0, %1}, %2;" : "=f"(r.x), "=f"(r.y) : "l"(v)); return r;
}

// 8x8 micro step with packed FMA: acc2[i][j2] += a[i] * b[j2 pair]
__device__ __forceinline__ void micro8x8(ull acc2[8][4],
                                         float4 a0, float4 a1,
                                         float4 b0, float4 b1)
{
    ull as[8];
    as[0]=splat2(a0.x); as[1]=splat2(a0.y); as[2]=splat2(a0.z); as[3]=splat2(a0.w);
    as[4]=splat2(a1.x); as[5]=splat2(a1.y); as[6]=splat2(a1.z); as[7]=splat2(a1.w);
    ull bp[4];
    bp[0]=pack2(b0.x,b0.y); bp[1]=pack2(b0.z,b0.w);
    bp[2]=pack2(b1.x,b1.y); bp[3]=pack2(b1.z,b1.w);
    #pragma unroll
    for (int i = 0; i < 8; i++)
        #pragma unroll
        for (int j = 0; j < 4; j++)
            ffma2(acc2[i][j], as[i], bp[j]);
}

// ---------------------------------------------------------------------------
// NT GEMM, 128x128 tile, BK=8, 256 threads, 8x8 per thread (split +-64).
// C[m,n] = scale * (sum_k (A[m,k](+A2[m,k]))*B[n,k] + bias[n]).  K = 1024.
// ---------------------------------------------------------------------------
template<bool SUM2>
__global__ __launch_bounds__(256) void gemm_nt_128(
    const float* __restrict__ A, const float* __restrict__ A2, Proj3 args)
{
    const int z = blockIdx.z;
    const float* __restrict__ B    = args.W[z];
    const float* __restrict__ bias = args.bias[z];
    float* __restrict__ C          = args.C[z];
    const float scale              = args.scale[z];

    __shared__ float As[8][132];
    __shared__ float Bs[8][132];
    const int tid = threadIdx.x;
    const int tx = tid & 15, ty = tid >> 4;
    const int m0 = blockIdx.y * 128, n0 = blockIdx.x * 128;
    const int lr = tid >> 1;
    const int lc = (tid & 1) * 4;
    const float* Ap  = A + (size_t)(m0 + lr) * DM + lc;
    const float* A2p = SUM2 ? (A2 + (size_t)(m0 + lr) * DM + lc) : nullptr;
    const float* Bp  = B + (size_t)(n0 + lr) * DM + lc;

    ull acc2[8][4] = {};
    float4 ra = *(const float4*)Ap;
    if (SUM2) {
        float4 r2 = *(const float4*)A2p;
        ra.x += r2.x; ra.y += r2.y; ra.z += r2.z; ra.w += r2.w;
    }
    float4 rb = *(const float4*)Bp;

    for (int k0 = 0; k0 < DM; k0 += 8) {
        __syncthreads();
        As[lc+0][lr]=ra.x; As[lc+1][lr]=ra.y; As[lc+2][lr]=ra.z; As[lc+3][lr]=ra.w;
        Bs[lc+0][lr]=rb.x; Bs[lc+1][lr]=rb.y; Bs[lc+2][lr]=rb.z; Bs[lc+3][lr]=rb.w;
        __syncthreads();
        if (k0 + 8 < DM) {
            ra = *(const float4*)(Ap + k0 + 8);
            if (SUM2) {
                float4 r2 = *(const float4*)(A2p + k0 + 8);
                ra.x += r2.x; ra.y += r2.y; ra.z += r2.z; ra.w += r2.w;
            }
            rb = *(const float4*)(Bp + k0 + 8);
        }
        #pragma unroll
        for (int k = 0; k < 8; k++) {
            float4 a0 = *(const float4*)&As[k][ty*4];
            float4 a1 = *(const float4*)&As[k][64 + ty*4];
            float4 b0 = *(const float4*)&Bs[k][tx*4];
            float4 b1 = *(const float4*)&Bs[k][64 + tx*4];
            micro8x8(acc2, a0, a1, b0, b1);
        }
    }

    float4 bb0 = *(const float4*)(bias + n0 + tx*4);
    float4 bb1 = *(const float4*)(bias + n0 + 64 + tx*4);
    #pragma unroll
    for (int i = 0; i < 8; i++) {
        int m = m0 + (i < 4 ? ty*4 + i : 64 + ty*4 + (i-4));
        float* Cr = C + (size_t)m * DM + n0;
        float2 p0 = unpack2(acc2[i][0]), p1 = unpack2(acc2[i][1]);
        float2 p2 = unpack2(acc2[i][2]), p3 = unpack2(acc2[i][3]);
        float4 o0, o1;
        o0.x = scale*(p0.x+bb0.x); o0.y = scale*(p0.y+bb0.y);
        o0.z = scale*(p1.x+bb0.z); o0.w = scale*(p1.y+bb0.w);
        o1.x = scale*(p2.x+bb1.x); o1.y = scale*(p2.y+bb1.y);
        o1.z = scale*(p3.x+bb1.z); o1.w = scale*(p3.y+bb1.w);
        *(float4*)(Cr + tx*4)      = o0;
        *(float4*)(Cr + 64 + tx*4) = o1;
    }
}

// ---------------------------------------------------------------------------
// scores[h,m,n] = sum_d Q[m,h*64+d]*K[n,h*64+d]; masked -> NEGV.
// ---------------------------------------------------------------------------
__global__ __launch_bounds__(256) void scores_128(
    const float* __restrict__ Q, const float* __restrict__ Km,
    const int* __restrict__ mask, float* __restrict__ attn)
{
    __shared__ float As[8][132];
    __shared__ float Bs[8][132];
    const int tid = threadIdx.x;
    const int tx = tid & 15, ty = tid >> 4;
    const int h = blockIdx.z;
    const int m0 = blockIdx.y * 128, n0 = blockIdx.x * 128;
    const int lr = tid >> 1;
    const int lc = (tid & 1) * 4;
    const float* Ap = Q  + (size_t)(m0 + lr) * DM + h*DH + lc;
    const float* Bp = Km + (size_t)(n0 + lr) * DM + h*DH + lc;

    ull acc2[8][4] = {};
    float4 ra = *(const float4*)Ap;
    float4 rb = *(const float4*)Bp;

    for (int k0 = 0; k0 < DH; k0 += 8) {
        __syncthreads();
        As[lc+0][lr]=ra.x; As[lc+1][lr]=ra.y; As[lc+2][lr]=ra.z; As[lc+3][lr]=ra.w;
        Bs[lc+0][lr]=rb.x; Bs[lc+1][lr]=rb.y; Bs[lc+2][lr]=rb.z; Bs[lc+3][lr]=rb.w;
        __syncthreads();
        if (k0 + 8 < DH) {
            ra = *(const float4*)(Ap + k0 + 8);
            rb = *(const float4*)(Bp + k0 + 8);
        }
        #pragma unroll
        for (int k = 0; k < 8; k++) {
            float4 a0 = *(const float4*)&As[k][ty*4];
            float4 a1 = *(const float4*)&As[k][64 + ty*4];
            float4 b0 = *(const float4*)&Bs[k][tx*4];
            float4 b1 = *(const float4*)&Bs[k][64 + tx*4];
            micro8x8(acc2, a0, a1, b0, b1);
        }
    }

    float* out = attn + (size_t)h * SQ * SQ;
    #pragma unroll
    for (int i = 0; i < 8; i++) {
        int m = m0 + (i < 4 ? ty*4 + i : 64 + ty*4 + (i-4));
        const int* mr = mask + (size_t)m * SQ + n0;
        float* orow = out + (size_t)m * SQ + n0;
        int4 mv0 = *(const int4*)(mr + tx*4);
        int4 mv1 = *(const int4*)(mr + 64 + tx*4);
        float2 p0 = unpack2(acc2[i][0]), p1 = unpack2(acc2[i][1]);
        float2 p2 = unpack2(acc2[i][2]), p3 = unpack2(acc2[i][3]);
        float4 o0, o1;
        o0.x = mv0.x ? NEGV : p0.x; o0.y = mv0.y ? NEGV : p0.y;
        o0.z = mv0.z ? NEGV : p1.x; o0.w = mv0.w ? NEGV : p1.y;
        o1.x = mv1.x ? NEGV : p2.x; o1.y = mv1.y ? NEGV : p2.y;
        o1.z = mv1.z ? NEGV : p3.x; o1.w = mv1.w ? NEGV : p3.y;
        *(float4*)(orow + tx*4)      = o0;
        *(float4*)(orow + 64 + tx*4) = o1;
    }
}

// ---------------------------------------------------------------------------
// In-place row softmax (rows of 2048).
// ---------------------------------------------------------------------------
__global__ __launch_bounds__(256) void softmax_kernel(float* __restrict__ attn)
{
    __shared__ float redm[8];
    __shared__ float reds[8];
    float* p = attn + (size_t)blockIdx.x * SQ;
    const int tid = threadIdx.x;

    float4 a = ((float4*)p)[tid];
    float4 b = ((float4*)p)[tid + 256];

    float m = fmaxf(fmaxf(fmaxf(a.x, a.y), fmaxf(a.z, a.w)),
                    fmaxf(fmaxf(b.x, b.y), fmaxf(b.z, b.w)));
    #pragma unroll
    for (int o = 16; o; o >>= 1) m = fmaxf(m, __shfl_xor_sync(0xffffffffu, m, o));
    if ((tid & 31) == 0) redm[tid >> 5] = m;
    __syncthreads();
    m = redm[0];
    #pragma unroll
    for (int i = 1; i < 8; i++) m = fmaxf(m, redm[i]);

    a.x = __expf(a.x - m); a.y = __expf(a.y - m); a.z = __expf(a.z - m); a.w = __expf(a.w - m);
    b.x = __expf(b.x - m); b.y = __expf(b.y - m); b.z = __expf(b.z - m); b.w = __expf(b.w - m);

    float s = (a.x + a.y) + (a.z + a.w) + (b.x + b.y) + (b.z + b.w);
    #pragma unroll
    for (int o = 16; o; o >>= 1) s += __shfl_xor_sync(0xffffffffu, s, o);
    if ((tid & 31) == 0) reds[tid >> 5] = s;
    __syncthreads();
    s = reds[0];
    #pragma unroll
    for (int i = 1; i < 8; i++) s += reds[i];

    float inv = 1.0f / s;
    a.x *= inv; a.y *= inv; a.z *= inv; a.w *= inv;
    b.x *= inv; b.y *= inv; b.z *= inv; b.w *= inv;

    ((float4*)p)[tid] = a;
    ((float4*)p)[tid + 256] = b;
}

// ---------------------------------------------------------------------------
// av partial: ctxPart[z][m, h*64+n] = sum_{k in z-half} attn[h,m,k]*V[k,h*64+n]
// 128x64 tile, BK=16, 128 threads, 8x8 per thread. grid.z = K-split (2).
// ---------------------------------------------------------------------------
__global__ __launch_bounds__(128) void av_128(
    const float* __restrict__ attn, const float* __restrict__ V,
    float* __restrict__ part0, float* __restrict__ part1)
{
    __shared__ float Ps[16][132];
    __shared__ float Vs[16][64];
    const int tid = threadIdx.x;
    const int tx = tid & 7, ty = tid >> 3;
    const int h = blockIdx.y;
    const int m0 = blockIdx.x * 128;
    const int kb = blockIdx.z * (SQ / 2);
    float* ctx = blockIdx.z ? part1 : part0;
    const float* P  = attn + (size_t)h * SQ * SQ + kb;
    const float* Vb = V + (size_t)kb * DM + h * DH;

    const int pr = tid >> 2;
    const int pc = (tid & 3) * 4;
    const int vr = tid >> 4;
    const int vc = (tid & 15) * 4;

    ull acc2[8][4] = {};
    float4 rp[4], rv[2];
    #pragma unroll
    for (int u = 0; u < 4; u++)
        rp[u] = *(const float4*)(P + (size_t)(m0 + pr + u*32) * SQ + pc);
    #pragma unroll
    for (int u = 0; u < 2; u++)
        rv[u] = *(const float4*)(Vb + (size_t)(vr + u*8) * DM + vc);

    for (int k0 = 0; k0 < SQ/2; k0 += 16) {
        __syncthreads();
        #pragma unroll
        for (int u = 0; u < 4; u++) {
            int r = pr + u*32;
            Ps[pc+0][r]=rp[u].x; Ps[pc+1][r]=rp[u].y;
            Ps[pc+2][r]=rp[u].z; Ps[pc+3][r]=rp[u].w;
        }
        #pragma unroll
        for (int u = 0; u < 2; u++)
            *(float4*)&Vs[vr + u*8][vc] = rv[u];
        __syncthreads();
        if (k0 + 16 < SQ/2) {
            #pragma unroll
            for (int u = 0; u < 4; u++)
                rp[u] = *(const float4*)(P + (size_t)(m0 + pr + u*32) * SQ + k0 + 16 + pc);
            #pragma unroll
            for (int u = 0; u < 2; u++)
                rv[u] = *(const float4*)(Vb + (size_t)(k0 + 16 + vr + u*8) * DM + vc);
        }
        #pragma unroll
        for (int k = 0; k < 16; k++) {
            float4 a0 = *(const float4*)&Ps[k][ty*4];
            float4 a1 = *(const float4*)&Ps[k][64 + ty*4];
            float4 b0 = *(const float4*)&Vs[k][tx*4];
            float4 b1 = *(const float4*)&Vs[k][32 + tx*4];
            micro8x8(acc2, a0, a1, b0, b1);
        }
    }

    #pragma unroll
    for (int i = 0; i < 8; i++) {
        int m = m0 + (i < 4 ? ty*4 + i : 64 + ty*4 + (i-4));
        float* Cr = ctx + (size_t)m * DM + h * DH;
        float2 p0 = unpack2(acc2[i][0]), p1 = unpack2(acc2[i][1]);
        float2 p2 = unpack2(acc2[i][2]), p3 = unpack2(acc2[i][3]);
        *(float4*)(Cr + tx*4)      = make_float4(p0.x, p0.y, p1.x, p1.y);
        *(float4*)(Cr + 32 + tx*4) = make_float4(p2.x, p2.y, p3.x, p3.y);
    }
}

// ---------------------------------------------------------------------------
extern "C" void kernel_launch(void* const* d_in, const int* in_sizes, int n_in,
                              void* d_out, int out_size)
{
    const float* X    = (const float*)d_in[0];
    const int*   mask = (const int*)d_in[1];
    const float* Wq   = (const float*)d_in[2];
    const float* bq   = (const float*)d_in[3];
    const float* Wk   = (const float*)d_in[4];
    const float* bk   = (const float*)d_in[5];
    const float* Wv   = (const float*)d_in[6];
    const float* bv   = (const float*)d_in[7];
    const float* Wo   = (const float*)d_in[8];
    const float* bo   = (const float*)d_in[9];

    float* out  = (float*)d_out;                 // (S, D)
    float* attn = out + (size_t)SQ * DM;         // (H, S, S)

    float *Qb, *Kb, *Vb, *Cb;
    cudaGetSymbolAddress((void**)&Qb, g_Q);
    cudaGetSymbolAddress((void**)&Kb, g_K);
    cudaGetSymbolAddress((void**)&Vb, g_V);
    cudaGetSymbolAddress((void**)&Cb, g_C);

    // QKV projections fused into one launch (scale 1/8 folded into Q)
    Proj3 pa;
    pa.W[0]=Wq; pa.W[1]=Wk; pa.W[2]=Wv;
    pa.bias[0]=bq; pa.bias[1]=bk; pa.bias[2]=bv;
    pa.C[0]=Qb; pa.C[1]=Kb; pa.C[2]=Vb;
    pa.scale[0]=0.125f; pa.scale[1]=1.0f; pa.scale[2]=1.0f;
    gemm_nt_128<false><<<dim3(8, 16, 3), 256>>>(X, nullptr, pa);

    scores_128<<<dim3(16, 16, 16), 256>>>(Qb, Kb, mask, attn);
    softmax_kernel<<<NH * SQ, 256>>>(attn);

    // av with K-split: partials into g_C (z=0) and g_Q (z=1; Q is dead now)
    av_128<<<dim3(16, 16, 2), 128>>>(attn, Vb, Cb, Qb);

    // out = (part0 + part1) @ Wo^T + bo   (reduction fused into A loads)
    Proj3 po;
    po.W[0]=Wo; po.bias[0]=bo; po.C[0]=out; po.scale[0]=1.0f;
    po.W[1]=Wo; po.bias[1]=bo; po.C[1]=out; po.scale[1]=1.0f;
    po.W[2]=Wo; po.bias[2]=bo; po.C[2]=out; po.scale[2]=1.0f;
    gemm_nt_128<true><<<dim3(8, 16, 1), 256>>>(Cb, Qb, po);
}

// round 7
// speedup vs baseline: 1.5753x; 1.5753x over previous
#include <cuda_runtime.h>

#define SQ 2048
#define DM 1024
#define NH 16
#define DH 64
#define NEGV -1e18f

// Scratch (device globals; no allocation allowed)
__device__ float g_Q[SQ * DM];   // Q; later reused as av partial-sum #1
__device__ float g_K[SQ * DM];
__device__ float g_V[SQ * DM];
__device__ float g_C[SQ * DM];   // av partial-sum #0

struct Proj3 {
    const float* W[3];
    const float* bias[3];
    float* C[3];
    float scale[3];
};

// ---- tf32 helpers ---------------------------------------------------------
__device__ __forceinline__ unsigned f2tf(float x) {
    unsigned r; asm("cvt.rna.tf32.f32 %0, %1;" : "=r"(r) : "f"(x)); return r;
}
// D(16x8) += A(16x8) * B(8x8); A row-major frag, B col-major frag.
__device__ __forceinline__ void mma8(float4& c,
    unsigned a0, unsigned a1, unsigned a2, unsigned a3,
    unsigned b0, unsigned b1)
{
    asm("mma.sync.aligned.m16n8k8.row.col.f32.tf32.tf32.f32 "
        "{%0,%1,%2,%3}, {%4,%5,%6,%7}, {%8,%9}, {%0,%1,%2,%3};"
        : "+f"(c.x), "+f"(c.y), "+f"(c.z), "+f"(c.w)
        : "r"(a0), "r"(a1), "r"(a2), "r"(a3), "r"(b0), "r"(b1));
}

// ---------------------------------------------------------------------------
// NT GEMM (tf32 MMA), 128x128 tile, BK=8, 256 threads = 8 warps (4x2).
// C[m,n] = scale * (sum_k (A[m,k](+A2[m,k]))*B[n,k] + bias[n]).  K = 1024.
// ---------------------------------------------------------------------------
template<bool SUM2>
__global__ __launch_bounds__(256) void proj_tf32(
    const float* __restrict__ A, const float* __restrict__ A2, Proj3 args)
{
    const int z = blockIdx.z;
    const float* __restrict__ B    = args.W[z];
    const float* __restrict__ bias = args.bias[z];
    float* __restrict__ C          = args.C[z];
    const float scale              = args.scale[z];

    __shared__ unsigned As[8][136];   // [k][m], tf32 bits
    __shared__ unsigned Bs[8][136];   // [k][n]
    const int tid = threadIdx.x;
    const int w = tid >> 5, lane = tid & 31, g = lane >> 2, t4 = lane & 3;
    const int wm = (w >> 1) * 32, wn = (w & 1) * 64;
    const int m0 = blockIdx.y * 128, n0 = blockIdx.x * 128;
    const int lr = tid >> 1, lc = (tid & 1) * 4;
    const float* Ap  = A + (size_t)(m0 + lr) * DM + lc;
    const float* A2p = SUM2 ? (A2 + (size_t)(m0 + lr) * DM + lc) : nullptr;
    const float* Bp  = B + (size_t)(n0 + lr) * DM + lc;

    float4 acc[2][8];
    #pragma unroll
    for (int i = 0; i < 2; i++)
        #pragma unroll
        for (int j = 0; j < 8; j++) acc[i][j] = make_float4(0,0,0,0);

    float4 ra = *(const float4*)Ap;
    if (SUM2) { float4 r2 = *(const float4*)A2p;
                ra.x+=r2.x; ra.y+=r2.y; ra.z+=r2.z; ra.w+=r2.w; }
    float4 rb = *(const float4*)Bp;

    for (int k0 = 0; k0 < DM; k0 += 8) {
        __syncthreads();
        As[lc+0][lr]=f2tf(ra.x); As[lc+1][lr]=f2tf(ra.y);
        As[lc+2][lr]=f2tf(ra.z); As[lc+3][lr]=f2tf(ra.w);
        Bs[lc+0][lr]=f2tf(rb.x); Bs[lc+1][lr]=f2tf(rb.y);
        Bs[lc+2][lr]=f2tf(rb.z); Bs[lc+3][lr]=f2tf(rb.w);
        __syncthreads();
        if (k0 + 8 < DM) {
            ra = *(const float4*)(Ap + k0 + 8);
            if (SUM2) { float4 r2 = *(const float4*)(A2p + k0 + 8);
                        ra.x+=r2.x; ra.y+=r2.y; ra.z+=r2.z; ra.w+=r2.w; }
            rb = *(const float4*)(Bp + k0 + 8);
        }
        unsigned bf[8][2];
        #pragma unroll
        for (int j = 0; j < 8; j++) {
            int cn = wn + j*8 + g;
            bf[j][0] = Bs[t4][cn];
            bf[j][1] = Bs[t4+4][cn];
        }
        #pragma unroll
        for (int i = 0; i < 2; i++) {
            int rm = wm + i*16 + g;
            unsigned a0 = As[t4][rm],   a1 = As[t4][rm+8];
            unsigned a2 = As[t4+4][rm], a3 = As[t4+4][rm+8];
            #pragma unroll
            for (int j = 0; j < 8; j++)
                mma8(acc[i][j], a0, a1, a2, a3, bf[j][0], bf[j][1]);
        }
    }

    #pragma unroll
    for (int i = 0; i < 2; i++) {
        int mb = m0 + wm + i*16;
        #pragma unroll
        for (int j = 0; j < 8; j++) {
            int n = n0 + wn + j*8 + t4*2;
            float2 bb = *(const float2*)(bias + n);
            float2 o0 = make_float2(scale*(acc[i][j].x + bb.x), scale*(acc[i][j].y + bb.y));
            float2 o1 = make_float2(scale*(acc[i][j].z + bb.x), scale*(acc[i][j].w + bb.y));
            *(float2*)(C + (size_t)(mb + g)     * DM + n) = o0;
            *(float2*)(C + (size_t)(mb + g + 8) * DM + n) = o1;
        }
    }
}

// ---------------------------------------------------------------------------
// scores[h,m,n] = sum_d Q[m,h*64+d]*K[n,h*64+d]; masked -> NEGV. tf32 MMA.
// 128x128 tile, K = 64 (8 chunks of 8), 256 threads (8 warps, 4x2).
// ---------------------------------------------------------------------------
__global__ __launch_bounds__(256) void scores_tf32(
    const float* __restrict__ Q, const float* __restrict__ Km,
    const int* __restrict__ mask, float* __restrict__ attn)
{
    __shared__ unsigned As[8][136];
    __shared__ unsigned Bs[8][136];
    const int tid = threadIdx.x;
    const int w = tid >> 5, lane = tid & 31, g = lane >> 2, t4 = lane & 3;
    const int wm = (w >> 1) * 32, wn = (w & 1) * 64;
    const int h = blockIdx.z;
    const int m0 = blockIdx.y * 128, n0 = blockIdx.x * 128;
    const int lr = tid >> 1, lc = (tid & 1) * 4;
    const float* Ap = Q  + (size_t)(m0 + lr) * DM + h*DH + lc;
    const float* Bp = Km + (size_t)(n0 + lr) * DM + h*DH + lc;

    float4 acc[2][8];
    #pragma unroll
    for (int i = 0; i < 2; i++)
        #pragma unroll
        for (int j = 0; j < 8; j++) acc[i][j] = make_float4(0,0,0,0);

    float4 ra = *(const float4*)Ap;
    float4 rb = *(const float4*)Bp;

    for (int k0 = 0; k0 < DH; k0 += 8) {
        __syncthreads();
        As[lc+0][lr]=f2tf(ra.x); As[lc+1][lr]=f2tf(ra.y);
        As[lc+2][lr]=f2tf(ra.z); As[lc+3][lr]=f2tf(ra.w);
        Bs[lc+0][lr]=f2tf(rb.x); Bs[lc+1][lr]=f2tf(rb.y);
        Bs[lc+2][lr]=f2tf(rb.z); Bs[lc+3][lr]=f2tf(rb.w);
        __syncthreads();
        if (k0 + 8 < DH) {
            ra = *(const float4*)(Ap + k0 + 8);
            rb = *(const float4*)(Bp + k0 + 8);
        }
        unsigned bf[8][2];
        #pragma unroll
        for (int j = 0; j < 8; j++) {
            int cn = wn + j*8 + g;
            bf[j][0] = Bs[t4][cn];
            bf[j][1] = Bs[t4+4][cn];
        }
        #pragma unroll
        for (int i = 0; i < 2; i++) {
            int rm = wm + i*16 + g;
            unsigned a0 = As[t4][rm],   a1 = As[t4][rm+8];
            unsigned a2 = As[t4+4][rm], a3 = As[t4+4][rm+8];
            #pragma unroll
            for (int j = 0; j < 8; j++)
                mma8(acc[i][j], a0, a1, a2, a3, bf[j][0], bf[j][1]);
        }
    }

    float* out = attn + (size_t)h * SQ * SQ;
    #pragma unroll
    for (int i = 0; i < 2; i++) {
        int mb = m0 + wm + i*16;
        #pragma unroll
        for (int j = 0; j < 8; j++) {
            int n = n0 + wn + j*8 + t4*2;
            int r0 = mb + g, r1 = mb + g + 8;
            int2 mv0 = *(const int2*)(mask + (size_t)r0 * SQ + n);
            int2 mv1 = *(const int2*)(mask + (size_t)r1 * SQ + n);
            float2 o0 = make_float2(mv0.x ? NEGV : acc[i][j].x, mv0.y ? NEGV : acc[i][j].y);
            float2 o1 = make_float2(mv1.x ? NEGV : acc[i][j].z, mv1.y ? NEGV : acc[i][j].w);
            *(float2*)(out + (size_t)r0 * SQ + n) = o0;
            *(float2*)(out + (size_t)r1 * SQ + n) = o1;
        }
    }
}

// ---------------------------------------------------------------------------
// In-place row softmax (rows of 2048).
// ---------------------------------------------------------------------------
__global__ __launch_bounds__(256) void softmax_kernel(float* __restrict__ attn)
{
    __shared__ float redm[8];
    __shared__ float reds[8];
    float* p = attn + (size_t)blockIdx.x * SQ;
    const int tid = threadIdx.x;

    float4 a = ((float4*)p)[tid];
    float4 b = ((float4*)p)[tid + 256];

    float m = fmaxf(fmaxf(fmaxf(a.x, a.y), fmaxf(a.z, a.w)),
                    fmaxf(fmaxf(b.x, b.y), fmaxf(b.z, b.w)));
    #pragma unroll
    for (int o = 16; o; o >>= 1) m = fmaxf(m, __shfl_xor_sync(0xffffffffu, m, o));
    if ((tid & 31) == 0) redm[tid >> 5] = m;
    __syncthreads();
    m = redm[0];
    #pragma unroll
    for (int i = 1; i < 8; i++) m = fmaxf(m, redm[i]);

    a.x = __expf(a.x - m); a.y = __expf(a.y - m); a.z = __expf(a.z - m); a.w = __expf(a.w - m);
    b.x = __expf(b.x - m); b.y = __expf(b.y - m); b.z = __expf(b.z - m); b.w = __expf(b.w - m);

    float s = (a.x + a.y) + (a.z + a.w) + (b.x + b.y) + (b.z + b.w);
    #pragma unroll
    for (int o = 16; o; o >>= 1) s += __shfl_xor_sync(0xffffffffu, s, o);
    if ((tid & 31) == 0) reds[tid >> 5] = s;
    __syncthreads();
    s = reds[0];
    #pragma unroll
    for (int i = 1; i < 8; i++) s += reds[i];

    float inv = 1.0f / s;
    a.x *= inv; a.y *= inv; a.z *= inv; a.w *= inv;
    b.x *= inv; b.y *= inv; b.z *= inv; b.w *= inv;

    ((float4*)p)[tid] = a;
    ((float4*)p)[tid + 256] = b;
}

// ---------------------------------------------------------------------------
// av partial (tf32 MMA, NN): ctxPart[z][m,h*64+n] = sum_{k in half z} attn*V.
// 128x64 tile, BK=16, 256 threads (8 warps, 4x2; warp = 32x32). grid.z = 2.
// ---------------------------------------------------------------------------
__global__ __launch_bounds__(256) void av_tf32(
    const float* __restrict__ attn, const float* __restrict__ V,
    float* __restrict__ part0, float* __restrict__ part1)
{
    __shared__ unsigned Ps[16][136];  // [k][m]
    __shared__ unsigned Vs[16][72];   // [k][n]
    const int tid = threadIdx.x;
    const int w = tid >> 5, lane = tid & 31, g = lane >> 2, t4 = lane & 3;
    const int wm = (w >> 1) * 32, wn = (w & 1) * 32;
    const int h = blockIdx.y;
    const int m0 = blockIdx.x * 128;
    const int kb = blockIdx.z * (SQ / 2);
    float* ctx = blockIdx.z ? part1 : part0;
    const float* P  = attn + (size_t)h * SQ * SQ + kb;
    const float* Vb = V + (size_t)kb * DM + h * DH;

    const int pr = tid >> 1;          // 0..127 (m row)
    const int pc = (tid & 1) * 8;     // 0 or 8 (k base; 8 floats per thread)
    const int vr = tid >> 4;          // 0..15 (k row)
    const int vc = (tid & 15) * 4;    // 0..60 (n)

    float4 acc[2][4];
    #pragma unroll
    for (int i = 0; i < 2; i++)
        #pragma unroll
        for (int j = 0; j < 4; j++) acc[i][j] = make_float4(0,0,0,0);

    float4 rp0 = *(const float4*)(P + (size_t)(m0 + pr) * SQ + pc);
    float4 rp1 = *(const float4*)(P + (size_t)(m0 + pr) * SQ + pc + 4);
    float4 rv  = *(const float4*)(Vb + (size_t)vr * DM + vc);

    for (int k0 = 0; k0 < SQ/2; k0 += 16) {
        __syncthreads();
        Ps[pc+0][pr]=f2tf(rp0.x); Ps[pc+1][pr]=f2tf(rp0.y);
        Ps[pc+2][pr]=f2tf(rp0.z); Ps[pc+3][pr]=f2tf(rp0.w);
        Ps[pc+4][pr]=f2tf(rp1.x); Ps[pc+5][pr]=f2tf(rp1.y);
        Ps[pc+6][pr]=f2tf(rp1.z); Ps[pc+7][pr]=f2tf(rp1.w);
        Vs[vr][vc+0]=f2tf(rv.x); Vs[vr][vc+1]=f2tf(rv.y);
        Vs[vr][vc+2]=f2tf(rv.z); Vs[vr][vc+3]=f2tf(rv.w);
        __syncthreads();
        if (k0 + 16 < SQ/2) {
            rp0 = *(const float4*)(P + (size_t)(m0 + pr) * SQ + k0 + 16 + pc);
            rp1 = *(const float4*)(P + (size_t)(m0 + pr) * SQ + k0 + 16 + pc + 4);
            rv  = *(const float4*)(Vb + (size_t)(k0 + 16 + vr) * DM + vc);
        }
        #pragma unroll
        for (int ks = 0; ks < 16; ks += 8) {
            unsigned bf[4][2];
            #pragma unroll
            for (int j = 0; j < 4; j++) {
                int cn = wn + j*8 + g;
                bf[j][0] = Vs[ks + t4][cn];
                bf[j][1] = Vs[ks + t4 + 4][cn];
            }
            #pragma unroll
            for (int i = 0; i < 2; i++) {
                int rm = wm + i*16 + g;
                unsigned a0 = Ps[ks+t4][rm],   a1 = Ps[ks+t4][rm+8];
                unsigned a2 = Ps[ks+t4+4][rm], a3 = Ps[ks+t4+4][rm+8];
                #pragma unroll
                for (int j = 0; j < 4; j++)
                    mma8(acc[i][j], a0, a1, a2, a3, bf[j][0], bf[j][1]);
            }
        }
    }

    #pragma unroll
    for (int i = 0; i < 2; i++) {
        int mb = m0 + wm + i*16;
        #pragma unroll
        for (int j = 0; j < 4; j++) {
            int n = h*DH + wn + j*8 + t4*2;
            *(float2*)(ctx + (size_t)(mb + g)     * DM + n) = make_float2(acc[i][j].x, acc[i][j].y);
            *(float2*)(ctx + (size_t)(mb + g + 8) * DM + n) = make_float2(acc[i][j].z, acc[i][j].w);
        }
    }
}

// ---------------------------------------------------------------------------
extern "C" void kernel_launch(void* const* d_in, const int* in_sizes, int n_in,
                              void* d_out, int out_size)
{
    const float* X    = (const float*)d_in[0];
    const int*   mask = (const int*)d_in[1];
    const float* Wq   = (const float*)d_in[2];
    const float* bq   = (const float*)d_in[3];
    const float* Wk   = (const float*)d_in[4];
    const float* bk   = (const float*)d_in[5];
    const float* Wv   = (const float*)d_in[6];
    const float* bv   = (const float*)d_in[7];
    const float* Wo   = (const float*)d_in[8];
    const float* bo   = (const float*)d_in[9];

    float* out  = (float*)d_out;                 // (S, D)
    float* attn = out + (size_t)SQ * DM;         // (H, S, S)

    float *Qb, *Kb, *Vb, *Cb;
    cudaGetSymbolAddress((void**)&Qb, g_Q);
    cudaGetSymbolAddress((void**)&Kb, g_K);
    cudaGetSymbolAddress((void**)&Vb, g_V);
    cudaGetSymbolAddress((void**)&Cb, g_C);

    // QKV projections fused into one launch (scale 1/8 folded into Q)
    Proj3 pa;
    pa.W[0]=Wq; pa.W[1]=Wk; pa.W[2]=Wv;
    pa.bias[0]=bq; pa.bias[1]=bk; pa.bias[2]=bv;
    pa.C[0]=Qb; pa.C[1]=Kb; pa.C[2]=Vb;
    pa.scale[0]=0.125f; pa.scale[1]=1.0f; pa.scale[2]=1.0f;
    proj_tf32<false><<<dim3(8, 16, 3), 256>>>(X, nullptr, pa);

    scores_tf32<<<dim3(16, 16, 16), 256>>>(Qb, Kb, mask, attn);
    softmax_kernel<<<NH * SQ, 256>>>(attn);

    // av with K-split: partials into g_C (z=0) and g_Q (z=1; Q is dead now)
    av_tf32<<<dim3(16, 16, 2), 256>>>(attn, Vb, Cb, Qb);

    // out = (part0 + part1) @ Wo^T + bo   (reduction fused into A loads)
    Proj3 po;
    po.W[0]=Wo; po.bias[0]=bo; po.C[0]=out; po.scale[0]=1.0f;
    po.W[1]=Wo; po.bias[1]=bo; po.C[1]=out; po.scale[1]=1.0f;
    po.W[2]=Wo; po.bias[2]=bo; po.C[2]=out; po.scale[2]=1.0f;
    proj_tf32<true><<<dim3(8, 16, 1), 256>>>(Cb, Qb, po);
}